// round 9
// baseline (speedup 1.0000x reference)
#include <cuda_runtime.h>
#include <cuda_bf16.h>
#include <stdint.h>

#define B_    128
#define S_    256
#define D_    512
#define H_    1024
#define NC_   128
#define NCTA  128

// ---------- device scratch (static globals; no runtime allocation) ----------
__device__ __align__(16) __nv_bfloat16 g_Wt[4u * 1024u * 1024u];  // Wt[g][j][k] = W_g[k][j], bf16
__device__ __align__(16) float         g_G[129 * 1024 * 4];       // G[c][j][gate] fp32
__device__ __align__(16) __nv_bfloat16 g_h[2][B_ * H_];           // double-buffered hidden (k-PERMUTED cols)
__device__ __align__(16) float         g_hfin[B_ * H_];           // final h, fp32, ORIGINAL col order
__device__ unsigned g_cnt;                                        // grid-barrier counter

// k-permutation inside each 16-block: perm position p holds original k = kmap[p&15] + (p & ~15)
__constant__ int c_kmap[16] = {0,1,8,9, 2,3,10,11, 4,5,12,13, 6,7,14,15};

// ---------- smem geometry of persistent kernel ----------
#define WK        1040                       /* W slice row stride (bf16): 520 words, %32==8 -> conflict-free */
#define HK        144                        /* h chunk row stride (bf16): 72 words, %32==8 -> conflict-free  */
#define WS_B      (32 * WK * 2)              /* 66560 B */
#define HS_B      (128 * HK * 2)             /* 36864 B per buffer */
#define CS_OFF    (WS_B + 2 * HS_B)          /* 140288 */
#define XS_OFF    (CS_OFF + 128 * 8 * 4)     /* 144384 */
#define SMEM_TOTAL (XS_OFF + 128 * 4)        /* 144896 */

// ---------- helpers ----------
__device__ __forceinline__ float sigm(float x) {                  // ~1e-6 accurate
    return __fdividef(1.f, 1.f + __expf(-x));
}
__device__ __forceinline__ float tanha(float x) {                 // 1 - 2/(e^{2x}+1)
    float e = __expf(2.f * x);
    return 1.f - __fdividef(2.f, e + 1.f);
}
__device__ __forceinline__ uint32_t smaddr(const void* p) {
    return (uint32_t)__cvta_generic_to_shared(p);
}
__device__ __forceinline__ void cp16(uint32_t dst, const void* src) {
    asm volatile("cp.async.cg.shared.global [%0], [%1], 16;\n" :: "r"(dst), "l"(src));
}
__device__ __forceinline__ void cp_commit() { asm volatile("cp.async.commit_group;\n"); }
__device__ __forceinline__ void mma16816(float (&c)[4],
                                         uint32_t a0, uint32_t a1, uint32_t a2, uint32_t a3,
                                         uint32_t b0, uint32_t b1) {
    asm volatile(
        "mma.sync.aligned.m16n8k16.row.col.f32.bf16.bf16.f32 "
        "{%0,%1,%2,%3}, {%4,%5,%6,%7}, {%8,%9}, {%0,%1,%2,%3};\n"
        : "+f"(c[0]), "+f"(c[1]), "+f"(c[2]), "+f"(c[3])
        : "r"(a0), "r"(a1), "r"(a2), "r"(a3), "r"(b0), "r"(b1));
}

// ---------- prep 1: per-launch state reset (graph replay must be deterministic) ----------
__global__ void init_state() {
    unsigned idx = blockIdx.x * blockDim.x + threadIdx.x;
    if (idx == 0) g_cnt = 0u;
    if (idx < B_ * H_) g_h[0][idx] = __float2bfloat16(0.f);
}

// ---------- prep 2: transpose+pack recurrent weights: Wt[g][j][k] = W_g[k][j] ----------
__global__ void transpose_W(const float* __restrict__ Wfh, const float* __restrict__ Wih,
                            const float* __restrict__ Wgh, const float* __restrict__ Woh) {
    __shared__ float tile[32][33];
    int g = blockIdx.z;
    const float* W = (g == 0) ? Wfh : (g == 1) ? Wih : (g == 2) ? Wgh : Woh;
    int k0 = blockIdx.x * 32, j0 = blockIdx.y * 32;
    int tx = threadIdx.x, ty = threadIdx.y;
#pragma unroll
    for (int i = 0; i < 32; i += 8)
        tile[ty + i][tx] = W[(size_t)(k0 + ty + i) * 1024 + j0 + tx];
    __syncthreads();
#pragma unroll
    for (int i = 0; i < 32; i += 8)
        g_Wt[((size_t)g * 1024 + (j0 + ty + i)) * 1024 + (k0 + tx)] =
            __float2bfloat16(tile[tx][ty + i]);
}

// ---------- prep 3: gate-input table G[c][j][g] = emb[c] . Wx_g[:,j] + b_g[j] ----------
__global__ void compute_G(const float* __restrict__ emb,
                          const float* __restrict__ Wfx, const float* __restrict__ Wix,
                          const float* __restrict__ Wgx, const float* __restrict__ Wox,
                          const float* __restrict__ bfp, const float* __restrict__ bip,
                          const float* __restrict__ bgp, const float* __restrict__ bop) {
    int g = blockIdx.z;
    const float* Wx   = (g == 0) ? Wfx : (g == 1) ? Wix : (g == 2) ? Wgx : Wox;
    const float* bias = (g == 0) ? bfp : (g == 1) ? bip : (g == 2) ? bgp : bop;
    int j0 = blockIdx.x * 128;
    int c0 = blockIdx.y * 16;
    __shared__ float es[16][512];
    int tid = threadIdx.x;
    for (int idx = tid; idx < 16 * 512; idx += 256) {
        int cc = idx >> 9, d = idx & 511;
        int c = c0 + cc;
        es[cc][d] = (c <= NC_) ? emb[c * 512 + d] : 0.f;
    }
    __syncthreads();
    int tc = tid >> 4, tj = tid & 15;
    float acc[8];
#pragma unroll
    for (int m = 0; m < 8; m++) acc[m] = 0.f;
    for (int d = 0; d < 512; d++) {
        float e = es[tc][d];
        const float* wr = Wx + (size_t)d * 1024 + j0 + tj;
#pragma unroll
        for (int m = 0; m < 8; m++) acc[m] = fmaf(e, wr[m * 16], acc[m]);
    }
    int c = c0 + tc;
    if (c <= NC_) {
#pragma unroll
        for (int m = 0; m < 8; m++) {
            int j = j0 + tj + m * 16;
            g_G[((size_t)c * 1024 + j) * 4 + g] = acc[m] + bias[j];
        }
    }
}

// ---------- the persistent recurrence kernel ----------
// 128 CTAs x 128 threads (4 warps). Warp w owns b-rows [32w, 32w+32) (two 16-row M-tiles).
// CTA owns output columns j = cta*8 .. cta*8+7 for all 4 gates (32 W columns in SMEM).
__global__ void __launch_bounds__(128, 1) lstm_persistent(const int* __restrict__ x) {
    extern __shared__ char smem[];
    __nv_bfloat16* ws  = (__nv_bfloat16*)smem;              // [32][WK]
    __nv_bfloat16* hsA = (__nv_bfloat16*)(smem + WS_B);     // 2 x [128][HK]
    float*         Cs  = (float*)(smem + CS_OFF);           // [128][8]
    int*           xs  = (int*)(smem + XS_OFF);             // [128]

    const int tid  = threadIdx.x;
    const int cta  = blockIdx.x;
    const int warp = tid >> 5;
    const int lane = tid & 31;
    const int r = lane >> 2, q = lane & 3;

    // one-time: load W slice into SMEM with k-permutation applied
    for (int idx = tid; idx < 32 * 1024; idx += 128) {
        int jj = idx >> 10, p = idx & 1023;
        int t = jj >> 3, jl = jj & 7;
        int korig = (p & ~15) + c_kmap[p & 15];
        ws[jj * WK + p] = g_Wt[((size_t)((t << 10) + cta * 8 + jl) << 10) + korig];
    }
    for (int idx = tid; idx < 1024; idx += 128) Cs[idx] = 0.f;
    __syncthreads();

    const float4* G4 = (const float4*)g_G;
    const int jl = 2 * q;                                   // original local j (pair base)
    const int jglob = cta * 8 + jl;
    const int gcol = (cta >> 1) * 16 + 4 * q + ((cta & 1) ? 2 : 0);  // permuted global h column

#pragma unroll 1
    for (int s = 0; s < S_; s++) {
        const int rbuf = s & 1, wbuf = rbuf ^ 1;
        const __nv_bfloat16* hg = g_h[rbuf];
        __nv_bfloat16*       hw = g_h[wbuf];

        xs[tid] = x[tid * S_ + s];

        float acc0[4][4], acc1[4][4];
#pragma unroll
        for (int t = 0; t < 4; t++)
#pragma unroll
            for (int i = 0; i < 4; i++) { acc0[t][i] = 0.f; acc1[t][i] = 0.f; }

        // prologue: chunk 0 -> buffer 0
        {
            const char* src = (const char*)hg;
            char* db = (char*)hsA;
#pragma unroll
            for (int i = 0; i < 16; i++) {
                int idx = tid + (i << 7);
                int b = idx >> 4, gs = idx & 15;
                cp16(smaddr(db + b * (HK * 2) + gs * 16), src + b * 2048 + gs * 16);
            }
            cp_commit();
        }

#pragma unroll 1
        for (int kc = 0; kc < 8; kc++) {
            if (kc < 7) {                                    // prefetch next chunk
                const char* src = (const char*)hg + (kc + 1) * 256;
                char* db = (char*)hsA + ((kc + 1) & 1) * HS_B;
#pragma unroll
                for (int i = 0; i < 16; i++) {
                    int idx = tid + (i << 7);
                    int b = idx >> 4, gs = idx & 15;
                    cp16(smaddr(db + b * (HK * 2) + gs * 16), src + b * 2048 + gs * 16);
                }
                cp_commit();
                asm volatile("cp.async.wait_group 1;\n");
            } else {
                asm volatile("cp.async.wait_group 0;\n");
            }
            __syncthreads();

            const __nv_bfloat16* hb = hsA + (kc & 1) * (128 * HK);
#pragma unroll
            for (int ks = 0; ks < 8; ks++) {
                int p0 = (ks << 4) + (q << 2);               // permuted k position
                const __nv_bfloat16* ab = hb + (warp * 32 + r) * HK + p0;
                uint2 A0 = *(const uint2*)(ab);              // (a0,a2) rows 32w+r
                uint2 A1 = *(const uint2*)(ab + 8 * HK);     // (a1,a3) rows 32w+r+8
                uint2 A2 = *(const uint2*)(ab + 16 * HK);
                uint2 A3 = *(const uint2*)(ab + 24 * HK);
                const __nv_bfloat16* wb = ws + r * WK + (kc << 7) + p0;
#pragma unroll
                for (int t = 0; t < 4; t++) {
                    uint2 Bv = *(const uint2*)(wb + t * 8 * WK);   // (b0,b1), col n=r, gate t
                    mma16816(acc0[t], A0.x, A1.x, A0.y, A1.y, Bv.x, Bv.y);
                    mma16816(acc1[t], A2.x, A3.x, A2.y, A3.y, Bv.x, Bv.y);
                }
            }
            __syncthreads();
        }

        // epilogue: register-resident gates -> C,h update
#pragma unroll
        for (int mt = 0; mt < 2; mt++) {
#pragma unroll
            for (int half = 0; half < 2; half++) {
                int bb = 32 * warp + 16 * mt + 8 * half + r;
                int cid = xs[bb];
                float4 Ga = G4[(size_t)cid * 1024 + jglob];
                float4 Gb = G4[(size_t)cid * 1024 + jglob + 1];
                int i0 = half * 2;
                float p00, p10, p20, p30, p01, p11, p21, p31;
                if (mt == 0) {
                    p00 = acc0[0][i0];     p10 = acc0[1][i0];     p20 = acc0[2][i0];     p30 = acc0[3][i0];
                    p01 = acc0[0][i0 + 1]; p11 = acc0[1][i0 + 1]; p21 = acc0[2][i0 + 1]; p31 = acc0[3][i0 + 1];
                } else {
                    p00 = acc1[0][i0];     p10 = acc1[1][i0];     p20 = acc1[2][i0];     p30 = acc1[3][i0];
                    p01 = acc1[0][i0 + 1]; p11 = acc1[1][i0 + 1]; p21 = acc1[2][i0 + 1]; p31 = acc1[3][i0 + 1];
                }
                float f0 = sigm(p00 + Ga.x), ii0 = sigm(p10 + Ga.y);
                float g0 = sigm(p20 + Ga.z), o0  = sigm(p30 + Ga.w);
                float f1 = sigm(p01 + Gb.x), ii1 = sigm(p11 + Gb.y);
                float g1 = sigm(p21 + Gb.z), o1  = sigm(p31 + Gb.w);
                float2 Co = *(float2*)&Cs[bb * 8 + jl];
                float Cn0 = (cid > 0) ? fmaf(Co.x, f0, g0 * ii0) : 0.f;
                float Cn1 = (cid > 0) ? fmaf(Co.y, f1, g1 * ii1) : 0.f;
                *(float2*)&Cs[bb * 8 + jl] = make_float2(Cn0, Cn1);
                float h0 = o0 * tanha(Cn0);
                float h1 = o1 * tanha(Cn1);
                *(__nv_bfloat162*)&hw[bb * 1024 + gcol] = __floats2bfloat162_rn(h0, h1);
                if (s == S_ - 1) {
                    g_hfin[bb * 1024 + jglob]     = h0;
                    g_hfin[bb * 1024 + jglob + 1] = h1;
                }
            }
        }

        // grid barrier (cumulative counter; reset by init_state each launch)
        __threadfence();
        __syncthreads();
        if (tid == 0) {
            atomicAdd(&g_cnt, 1u);
            unsigned target = (unsigned)(s + 1) * NCTA, v;
            do {
                asm volatile("ld.acquire.gpu.u32 %0, [%1];" : "=r"(v) : "l"(&g_cnt) : "memory");
            } while (v < target);
            __threadfence();
        }
        __syncthreads();
    }
}

// ---------- final projection + log_softmax ----------
__global__ void proj_kernel(const float* __restrict__ Wph, const float* __restrict__ bp,
                            float* __restrict__ out) {
    __shared__ float hrow[1024];
    __shared__ float redmax[4];
    __shared__ float redsum[4];
    int b = blockIdx.x, tid = threadIdx.x;
    for (int i = tid; i < 1024; i += 128) hrow[i] = g_hfin[b * 1024 + i];
    __syncthreads();
    float acc = bp[tid];
#pragma unroll 8
    for (int j = 0; j < 1024; j++) acc = fmaf(hrow[j], Wph[j * 128 + tid], acc);
    float m = acc;
#pragma unroll
    for (int o = 16; o; o >>= 1) m = fmaxf(m, __shfl_xor_sync(0xffffffffu, m, o));
    if ((tid & 31) == 0) redmax[tid >> 5] = m;
    __syncthreads();
    m = fmaxf(fmaxf(redmax[0], redmax[1]), fmaxf(redmax[2], redmax[3]));
    float e = expf(acc - m);
    float ss = e;
#pragma unroll
    for (int o = 16; o; o >>= 1) ss += __shfl_xor_sync(0xffffffffu, ss, o);
    if ((tid & 31) == 0) redsum[tid >> 5] = ss;
    __syncthreads();
    float tot = redsum[0] + redsum[1] + redsum[2] + redsum[3];
    out[b * 128 + tid] = acc - m - logf(tot);
}

// ---------- launch ----------
extern "C" void kernel_launch(void* const* d_in, const int* in_sizes, int n_in,
                              void* d_out, int out_size) {
    const int*   x   = (const int*)d_in[0];
    const float* emb = (const float*)d_in[1];
    const float* Wfx = (const float*)d_in[2];
    const float* Wfh = (const float*)d_in[3];
    const float* bfp = (const float*)d_in[4];
    const float* Wix = (const float*)d_in[5];
    const float* Wih = (const float*)d_in[6];
    const float* bip = (const float*)d_in[7];
    const float* Wgx = (const float*)d_in[8];
    const float* Wgh = (const float*)d_in[9];
    const float* bgp = (const float*)d_in[10];
    const float* Wox = (const float*)d_in[11];
    const float* Woh = (const float*)d_in[12];
    const float* bop = (const float*)d_in[13];
    const float* Wph = (const float*)d_in[14];
    const float* bpp = (const float*)d_in[15];
    float* out = (float*)d_out;

    cudaFuncSetAttribute(lstm_persistent, cudaFuncAttributeMaxDynamicSharedMemorySize, SMEM_TOTAL);

    init_state<<<512, 256>>>();
    transpose_W<<<dim3(32, 32, 4), dim3(32, 8)>>>(Wfh, Wih, Wgh, Woh);
    compute_G<<<dim3(8, 9, 4), 256>>>(emb, Wfx, Wix, Wgx, Wox, bfp, bip, bgp, bop);
    lstm_persistent<<<NCTA, 128, SMEM_TOTAL>>>(x);
    proj_kernel<<<128, 128>>>(Wph, bpp, out);
}

// round 13
// speedup vs baseline: 1.2080x; 1.2080x over previous
#include <cuda_runtime.h>
#include <cuda_bf16.h>
#include <stdint.h>

#define B_    128
#define S_    256
#define H_    1024
#define NC_   128
#define NCTA  128
#define NTHR  160                 /* 4 consumer warps + 1 producer warp */
#define NJ    8                   /* j columns per CTA; N = 32 B-rows (4 gates x 8 j) */

// ---------------- device scratch (static; no runtime allocation) ----------------
__device__ __align__(16) __nv_bfloat16 g_Wt[4u * 1024u * 1024u];  // Wt[g][j][k] = W_g[k][j], bf16
__device__ __align__(16) float         g_G[129 * 1024 * 4];       // G[c][j][gate] fp32
// hidden state, double buffered, k16-BLOCK-MAJOR: [64 blocks][128 b][16 halves(perm)]
__device__ __align__(16) __nv_bfloat16 g_h[2][B_ * H_];
__device__ __align__(16) float         g_hfin[B_ * H_];           // final h fp32, orig layout
__device__ unsigned g_cnt;                                        // grid-barrier counter

// perm position p within a k16 block holds orig k = (p & ~15) + kmap[p & 15]
__constant__ int c_kmap[16] = {0,1,8,9, 2,3,10,11, 4,5,12,13, 6,7,14,15};

// ---------------- smem geometry ----------------
#define WK        1040                    /* W row stride in halves; 8n+2q banks conflict-free */
#define WS_B      (32 * WK * 2)           /* 66560 B */
#define CHUNK_B   16384                   /* one 64-k chunk: 4 blocks x 4096 B, dense */
#define SMEM_TOTAL (128 + WS_B + 4 * CHUNK_B)   /* 128 ctrl + W + 4-ring = 132224 B */

// ---------------- helpers ----------------
__device__ __forceinline__ float sigm(float x) {
    return __fdividef(1.f, 1.f + __expf(-x));
}
__device__ __forceinline__ float tanha(float x) {
    float e = __expf(2.f * x);
    return 1.f - __fdividef(2.f, e + 1.f);
}
__device__ __forceinline__ void mma16816(float (&c)[4],
                                         uint32_t a0, uint32_t a1, uint32_t a2, uint32_t a3,
                                         uint32_t b0, uint32_t b1) {
    asm volatile(
        "mma.sync.aligned.m16n8k16.row.col.f32.bf16.bf16.f32 "
        "{%0,%1,%2,%3}, {%4,%5,%6,%7}, {%8,%9}, {%0,%1,%2,%3};\n"
        : "+f"(c[0]), "+f"(c[1]), "+f"(c[2]), "+f"(c[3])
        : "r"(a0), "r"(a1), "r"(a2), "r"(a3), "r"(b0), "r"(b1));
}
#define MBAR_INIT(a, c) \
    asm volatile("mbarrier.init.shared.b64 [%0], %1;" :: "r"(a), "r"(c) : "memory")
#define MBAR_ARRIVE(a) \
    asm volatile("mbarrier.arrive.shared.b64 _, [%0];" :: "r"(a) : "memory")
#define MBAR_EXPECT_TX(a, n) \
    asm volatile("mbarrier.arrive.expect_tx.shared.b64 _, [%0], %1;" :: "r"(a), "r"(n) : "memory")
#define MBAR_WAIT(a, par) do {                                                      \
    uint32_t _m = (a), _p = (par), _d;                                              \
    asm volatile("{\n\t.reg .pred p;\n\t"                                           \
        "mbarrier.try_wait.parity.acquire.cta.shared::cta.b64 p, [%1], %2;\n\t"     \
        "selp.b32 %0, 1, 0, p;\n\t}" : "=r"(_d) : "r"(_m), "r"(_p) : "memory");     \
    if (!_d) {                                                                      \
        asm volatile("{\n\t.reg .pred P1;\n\tWL%=: \n\t"                            \
            "mbarrier.try_wait.parity.acquire.cta.shared::cta.b64 P1, [%0], %1, 0x989680;\n\t" \
            "@P1 bra.uni WD%=;\n\tbra.uni WL%=;\n\tWD%=: \n\t}"                     \
            :: "r"(_m), "r"(_p) : "memory");                                        \
    }                                                                               \
} while (0)
__device__ __forceinline__ void bulk_cp(uint32_t dst, const void* src, uint32_t bytes,
                                        uint32_t mbar) {
    asm volatile(
        "cp.async.bulk.shared::cta.global.mbarrier::complete_tx::bytes [%0], [%1], %2, [%3];"
        :: "r"(dst), "l"(src), "r"(bytes), "r"(mbar) : "memory");
}

// ---------------- prep 1: per-launch reset ----------------
__global__ void init_state() {
    unsigned idx = blockIdx.x * blockDim.x + threadIdx.x;
    if (idx == 0) g_cnt = 0u;
    if (idx < B_ * H_) g_h[0][idx] = __float2bfloat16(0.f);
}

// ---------------- prep 2: transpose+pack recurrent weights ----------------
__global__ void transpose_W(const float* __restrict__ Wfh, const float* __restrict__ Wih,
                            const float* __restrict__ Wgh, const float* __restrict__ Woh) {
    __shared__ float tile[32][33];
    int g = blockIdx.z;
    const float* W = (g == 0) ? Wfh : (g == 1) ? Wih : (g == 2) ? Wgh : Woh;
    int k0 = blockIdx.x * 32, j0 = blockIdx.y * 32;
    int tx = threadIdx.x, ty = threadIdx.y;
#pragma unroll
    for (int i = 0; i < 32; i += 8)
        tile[ty + i][tx] = W[(size_t)(k0 + ty + i) * 1024 + j0 + tx];
    __syncthreads();
#pragma unroll
    for (int i = 0; i < 32; i += 8)
        g_Wt[((size_t)g * 1024 + (j0 + ty + i)) * 1024 + (k0 + tx)] =
            __float2bfloat16(tile[tx][ty + i]);
}

// ---------------- prep 3: gate-input table G[c][j][g] ----------------
__global__ void compute_G(const float* __restrict__ emb,
                          const float* __restrict__ Wfx, const float* __restrict__ Wix,
                          const float* __restrict__ Wgx, const float* __restrict__ Wox,
                          const float* __restrict__ bfp, const float* __restrict__ bip,
                          const float* __restrict__ bgp, const float* __restrict__ bop) {
    int g = blockIdx.z;
    const float* Wx   = (g == 0) ? Wfx : (g == 1) ? Wix : (g == 2) ? Wgx : Wox;
    const float* bias = (g == 0) ? bfp : (g == 1) ? bip : (g == 2) ? bgp : bop;
    int j0 = blockIdx.x * 128, c0 = blockIdx.y * 16;
    __shared__ float es[16][512];
    int tid = threadIdx.x;
    for (int idx = tid; idx < 16 * 512; idx += 256) {
        int cc = idx >> 9, d = idx & 511;
        int c = c0 + cc;
        es[cc][d] = (c <= NC_) ? emb[c * 512 + d] : 0.f;
    }
    __syncthreads();
    int tc = tid >> 4, tj = tid & 15;
    float acc[8];
#pragma unroll
    for (int m = 0; m < 8; m++) acc[m] = 0.f;
    for (int d = 0; d < 512; d++) {
        float e = es[tc][d];
        const float* wr = Wx + (size_t)d * 1024 + j0 + tj;
#pragma unroll
        for (int m = 0; m < 8; m++) acc[m] = fmaf(e, wr[m * 16], acc[m]);
    }
    int c = c0 + tc;
    if (c <= NC_) {
#pragma unroll
        for (int m = 0; m < 8; m++) {
            int j = j0 + tj + m * 16;
            g_G[((size_t)c * 1024 + j) * 4 + g] = acc[m] + bias[j];
        }
    }
}

// ---------------- persistent recurrence ----------------
// 128 CTAs x 160 threads. Warps 0-3: mma consumers (warp w owns b-rows 32w..32w+31,
// all N=32: gate-tile t = n8-tile). Warp 4: bulk-copy producer.
// W smem rows n = gate*8 + jl; accum tile t = gate, fragment n-lane = jl = r.
__global__ void __launch_bounds__(NTHR, 1) lstm_persistent(const int* __restrict__ x) {
    extern __shared__ char smem[];
    uint32_t sbase = (uint32_t)__cvta_generic_to_shared(smem);
    const uint32_t mb_full = sbase;          // 4 x 8 B
    const uint32_t mb_cons = sbase + 32;     // 4 x 8 B
    __nv_bfloat16* ws = (__nv_bfloat16*)(smem + 128);
    char*          hring = smem + 128 + WS_B;
    const uint32_t hring_s = sbase + 128 + WS_B;

    const int tid = threadIdx.x, warp = tid >> 5, lane = tid & 31;
    const int r = lane >> 2, q = lane & 3;
    const int cta = blockIdx.x;

    if (tid == 0) {
        for (int i = 0; i < 4; i++) { MBAR_INIT(mb_full + 8 * i, 1); MBAR_INIT(mb_cons + 8 * i, 128); }
    }
    // one-time W fill: ws[n][p] = Wt[gate][cta*8+jl][perm^-1(p)], n = gate*8+jl
    for (int t = tid; t < 32 * 1024; t += NTHR) {
        int n = t >> 10, p = t & 1023;
        int gate = n >> 3, jl = n & 7;
        int korig = (p & ~15) + c_kmap[p & 15];
        ws[n * WK + p] = g_Wt[((size_t)(gate << 10) + cta * NJ + jl) * 1024 + korig];
    }
    __syncthreads();

    float C[2][2][2];                        // [mt][hh][jj], register-resident cell state
#pragma unroll
    for (int a = 0; a < 2; a++)
#pragma unroll
        for (int b = 0; b < 2; b++) { C[a][b][0] = 0.f; C[a][b][1] = 0.f; }

    const float4* G4 = (const float4*)g_G;

#pragma unroll 1
    for (int s = 0; s < S_; s++) {
        const char* hg = (const char*)g_h[s & 1];
        char*       hw = (char*)g_h[(s & 1) ^ 1];

        if (warp == 4) {                     // ---------------- producer ----------------
            if (lane == 0) {
#pragma unroll 1
                for (int kc = 0; kc < 16; kc++) {
                    int buf = kc & 3, t4 = kc >> 2;
                    if (!(s == 0 && kc < 4)) MBAR_WAIT(mb_cons + 8 * buf, (t4 + 1) & 1);
                    MBAR_EXPECT_TX(mb_full + 8 * buf, (uint32_t)CHUNK_B);
                    bulk_cp(hring_s + (uint32_t)buf * CHUNK_B, hg + (size_t)kc * CHUNK_B,
                            CHUNK_B, mb_full + 8 * buf);
                }
            }
        } else {                             // ---------------- consumers ----------------
            // prefetch token ids for this thread's 4 b-rows (hides L2 latency under mma)
            int cid[4];
#pragma unroll
            for (int mt = 0; mt < 2; mt++)
#pragma unroll
                for (int hh = 0; hh < 2; hh++)
                    cid[mt * 2 + hh] = __ldg(&x[(32 * warp + 16 * mt + 8 * hh + r) * S_ + s]);

            float acc[2][4][4];
#pragma unroll
            for (int mt = 0; mt < 2; mt++)
#pragma unroll
                for (int t = 0; t < 4; t++)
#pragma unroll
                    for (int i = 0; i < 4; i++) acc[mt][t][i] = 0.f;

#pragma unroll 1
            for (int kc = 0; kc < 16; kc++) {
                int buf = kc & 3, t4 = kc >> 2;
                MBAR_WAIT(mb_full + 8 * buf, t4 & 1);
                const char* hb = hring + (size_t)buf * CHUNK_B;
#pragma unroll
                for (int ks = 0; ks < 4; ks++) {
                    // A fragments: uint2 at perm bytes q*8 of row b in block ks
                    const char* ab = hb + ks * 4096 + q * 8;
                    uint2 A00 = *(const uint2*)(ab + (32 * warp + r) * 32);
                    uint2 A01 = *(const uint2*)(ab + (32 * warp + r + 8) * 32);
                    uint2 A10 = *(const uint2*)(ab + (32 * warp + 16 + r) * 32);
                    uint2 A11 = *(const uint2*)(ab + (32 * warp + 24 + r) * 32);
                    // B fragments: row n = t*8 + r, perm halves kc*64+ks*16+q*4
                    const __nv_bfloat16* wb = ws + (size_t)r * WK + kc * 64 + ks * 16 + q * 4;
#pragma unroll
                    for (int t = 0; t < 4; t++) {
                        uint2 Bv = *(const uint2*)(wb + (size_t)t * 8 * WK);
                        mma16816(acc[0][t], A00.x, A01.x, A00.y, A01.y, Bv.x, Bv.y);
                        mma16816(acc[1][t], A10.x, A11.x, A10.y, A11.y, Bv.x, Bv.y);
                    }
                }
                MBAR_ARRIVE(mb_cons + 8 * buf);
            }

            // ---- epilogue: gates, C, h (register-resident) ----
            const int bk = cta >> 1;                       // k16 block of this CTA's j's
            const int poff = 8 * q + 4 * (cta & 1);        // byte offset of j-pair in block row
#pragma unroll
            for (int mt = 0; mt < 2; mt++) {
#pragma unroll
                for (int hh = 0; hh < 2; hh++) {
                    int b = 32 * warp + 16 * mt + 8 * hh + r;
                    int id = cid[mt * 2 + hh];
                    float4 Ga = __ldg(&G4[(size_t)id * 1024 + cta * NJ + 2 * q]);
                    float4 Gb = __ldg(&G4[(size_t)id * 1024 + cta * NJ + 2 * q + 1]);
                    int c0 = hh * 2;
                    float f0 = sigm(acc[mt][0][c0] + Ga.x);
                    float i0 = sigm(acc[mt][1][c0] + Ga.y);
                    float g0 = sigm(acc[mt][2][c0] + Ga.z);
                    float o0 = sigm(acc[mt][3][c0] + Ga.w);
                    float f1 = sigm(acc[mt][0][c0 + 1] + Gb.x);
                    float i1 = sigm(acc[mt][1][c0 + 1] + Gb.y);
                    float g1 = sigm(acc[mt][2][c0 + 1] + Gb.z);
                    float o1 = sigm(acc[mt][3][c0 + 1] + Gb.w);
                    float Cn0 = (id > 0) ? fmaf(C[mt][hh][0], f0, g0 * i0) : 0.f;
                    float Cn1 = (id > 0) ? fmaf(C[mt][hh][1], f1, g1 * i1) : 0.f;
                    C[mt][hh][0] = Cn0;
                    C[mt][hh][1] = Cn1;
                    float h0 = o0 * tanha(Cn0);
                    float h1 = o1 * tanha(Cn1);
                    __nv_bfloat162 hp = __floats2bfloat162_rn(h0, h1);
                    *(uint32_t*)(hw + (size_t)bk * 4096 + b * 32 + poff) = *(uint32_t*)&hp;
                    if (s == S_ - 1) {
                        g_hfin[(size_t)b * 1024 + cta * NJ + 2 * q]     = h0;
                        g_hfin[(size_t)b * 1024 + cta * NJ + 2 * q + 1] = h1;
                    }
                }
            }
            asm volatile("fence.proxy.async;" ::: "memory");  // generic STG -> next-step bulk reads
        }

        // grid barrier (cumulative counter; reset each launch)
        __threadfence();
        __syncthreads();
        if (tid == 0) {
            atomicAdd(&g_cnt, 1u);
            unsigned target = (unsigned)(s + 1) * NCTA, v;
            do {
                asm volatile("ld.acquire.gpu.u32 %0, [%1];" : "=r"(v) : "l"(&g_cnt) : "memory");
            } while (v < target);
            __threadfence();
        }
        __syncthreads();
    }
}

// ---------------- final projection + log_softmax ----------------
__global__ void proj_kernel(const float* __restrict__ Wph, const float* __restrict__ bp,
                            float* __restrict__ out) {
    __shared__ float hrow[1024];
    __shared__ float redmax[4], redsum[4];
    int b = blockIdx.x, tid = threadIdx.x;
    for (int i = tid; i < 1024; i += 128) hrow[i] = g_hfin[b * 1024 + i];
    __syncthreads();
    float acc = bp[tid];
#pragma unroll 8
    for (int j = 0; j < 1024; j++) acc = fmaf(hrow[j], Wph[j * 128 + tid], acc);
    float m = acc;
#pragma unroll
    for (int o = 16; o; o >>= 1) m = fmaxf(m, __shfl_xor_sync(0xffffffffu, m, o));
    if ((tid & 31) == 0) redmax[tid >> 5] = m;
    __syncthreads();
    m = fmaxf(fmaxf(redmax[0], redmax[1]), fmaxf(redmax[2], redmax[3]));
    float e = expf(acc - m);
    float ss = e;
#pragma unroll
    for (int o = 16; o; o >>= 1) ss += __shfl_xor_sync(0xffffffffu, ss, o);
    if ((tid & 31) == 0) redsum[tid >> 5] = ss;
    __syncthreads();
    float tot = redsum[0] + redsum[1] + redsum[2] + redsum[3];
    out[b * 128 + tid] = acc - m - logf(tot);
}

// ---------------- launch ----------------
extern "C" void kernel_launch(void* const* d_in, const int* in_sizes, int n_in,
                              void* d_out, int out_size) {
    const int*   x   = (const int*)d_in[0];
    const float* emb = (const float*)d_in[1];
    const float* Wfx = (const float*)d_in[2];
    const float* Wfh = (const float*)d_in[3];
    const float* bfp = (const float*)d_in[4];
    const float* Wix = (const float*)d_in[5];
    const float* Wih = (const float*)d_in[6];
    const float* bip = (const float*)d_in[7];
    const float* Wgx = (const float*)d_in[8];
    const float* Wgh = (const float*)d_in[9];
    const float* bgp = (const float*)d_in[10];
    const float* Wox = (const float*)d_in[11];
    const float* Woh = (const float*)d_in[12];
    const float* bop = (const float*)d_in[13];
    const float* Wph = (const float*)d_in[14];
    const float* bpp = (const float*)d_in[15];
    float* out = (float*)d_out;

    cudaFuncSetAttribute(lstm_persistent, cudaFuncAttributeMaxDynamicSharedMemorySize, SMEM_TOTAL);

    init_state<<<512, 256>>>();
    transpose_W<<<dim3(32, 32, 4), dim3(32, 8)>>>(Wfh, Wih, Wgh, Woh);
    compute_G<<<dim3(8, 9, 4), 256>>>(emb, Wfx, Wix, Wgx, Wox, bfp, bip, bgp, bop);
    lstm_persistent<<<NCTA, NTHR, SMEM_TOTAL>>>(x);
    proj_kernel<<<128, 128>>>(Wph, bpp, out);
}

// round 17
// speedup vs baseline: 1.4488x; 1.1994x over previous
#include <cuda_runtime.h>
#include <cuda_bf16.h>
#include <stdint.h>

#define B_    128
#define S_    256
#define H_    1024
#define NC_   128
#define NCTA  128
#define NTHR  320                 /* 8 consumer warps + 2 producer warps */
#define NJ    8                   /* j columns per CTA; N = 32 B-rows (4 gates x 8 j) */

// ---------------- device scratch (static; no runtime allocation) ----------------
__device__ __align__(16) __nv_bfloat16 g_Wt[4u * 1024u * 1024u];  // Wt[g][j][k] = W_g[k][j], bf16
__device__ __align__(16) float         g_G[129 * 1024 * 4];       // G[c][j][gate] fp32
// hidden state, double buffered, k16-BLOCK-MAJOR: [64 blocks][128 b][16 halves(perm)]
__device__ __align__(16) __nv_bfloat16 g_h[2][B_ * H_];
__device__ __align__(16) float         g_hfin[B_ * H_];           // final h fp32, orig layout
__device__ unsigned g_prod[16];                                   // per-group progress flags

// perm position p within a k16 block holds orig k = (p & ~15) + kmap[p & 15]
__constant__ int c_kmap[16] = {0,1,8,9, 2,3,10,11, 4,5,12,13, 6,7,14,15};

// ---------------- smem geometry ----------------
#define WK        1040                    /* W row stride in halves; conflict-free */
#define WS_B      (32 * WK * 2)           /* 66560 B */
#define CHUNK_B   16384                   /* one 64-k chunk: 4 blocks x 4096 B */
#define RING_OFF  (128 + WS_B)
#define REDS_OFF  (RING_OFF + 8 * CHUNK_B)
#define SMEM_TOTAL (REDS_OFF + 16384)     /* 128 ctrl + W + 8-ring + 16KB reduce = 214144 */

// ---------------- helpers ----------------
__device__ __forceinline__ float sigm(float x) {
    return __fdividef(1.f, 1.f + __expf(-x));
}
__device__ __forceinline__ float tanha(float x) {
    float e = __expf(2.f * x);
    return 1.f - __fdividef(2.f, e + 1.f);
}
__device__ __forceinline__ void mma16816(float (&c)[4],
                                         uint32_t a0, uint32_t a1, uint32_t a2, uint32_t a3,
                                         uint32_t b0, uint32_t b1) {
    asm volatile(
        "mma.sync.aligned.m16n8k16.row.col.f32.bf16.bf16.f32 "
        "{%0,%1,%2,%3}, {%4,%5,%6,%7}, {%8,%9}, {%0,%1,%2,%3};\n"
        : "+f"(c[0]), "+f"(c[1]), "+f"(c[2]), "+f"(c[3])
        : "r"(a0), "r"(a1), "r"(a2), "r"(a3), "r"(b0), "r"(b1));
}
#define MBAR_INIT(a, c) \
    asm volatile("mbarrier.init.shared.b64 [%0], %1;" :: "r"(a), "r"(c) : "memory")
#define MBAR_ARRIVE(a) \
    asm volatile("mbarrier.arrive.shared.b64 _, [%0];" :: "r"(a) : "memory")
#define MBAR_EXPECT_TX(a, n) \
    asm volatile("mbarrier.arrive.expect_tx.shared.b64 _, [%0], %1;" :: "r"(a), "r"(n) : "memory")
#define MBAR_WAIT(a, par) do {                                                      \
    uint32_t _m = (a), _p = (par), _d;                                              \
    asm volatile("{\n\t.reg .pred p;\n\t"                                           \
        "mbarrier.try_wait.parity.acquire.cta.shared::cta.b64 p, [%1], %2;\n\t"     \
        "selp.b32 %0, 1, 0, p;\n\t}" : "=r"(_d) : "r"(_m), "r"(_p) : "memory");     \
    if (!_d) {                                                                      \
        asm volatile("{\n\t.reg .pred P1;\n\tWL%=: \n\t"                            \
            "mbarrier.try_wait.parity.acquire.cta.shared::cta.b64 P1, [%0], %1, 0x989680;\n\t" \
            "@P1 bra.uni WD%=;\n\tbra.uni WL%=;\n\tWD%=: \n\t}"                     \
            :: "r"(_m), "r"(_p) : "memory");                                        \
    }                                                                               \
} while (0)
#define BARX(id, cnt) \
    asm volatile("bar.sync %0, %1;" :: "r"(id), "r"(cnt) : "memory")
__device__ __forceinline__ void bulk_cp(uint32_t dst, const void* src, uint32_t bytes,
                                        uint32_t mbar) {
    asm volatile(
        "cp.async.bulk.shared::cta.global.mbarrier::complete_tx::bytes [%0], [%1], %2, [%3];"
        :: "r"(dst), "l"(src), "r"(bytes), "r"(mbar) : "memory");
}

// ---------------- prep 1: per-launch reset ----------------
__global__ void init_state() {
    unsigned idx = blockIdx.x * blockDim.x + threadIdx.x;
    if (idx < 16) g_prod[idx] = 0u;
    if (idx < B_ * H_) g_h[0][idx] = __float2bfloat16(0.f);
}

// ---------------- prep 2: transpose+pack recurrent weights ----------------
__global__ void transpose_W(const float* __restrict__ Wfh, const float* __restrict__ Wih,
                            const float* __restrict__ Wgh, const float* __restrict__ Woh) {
    __shared__ float tile[32][33];
    int g = blockIdx.z;
    const float* W = (g == 0) ? Wfh : (g == 1) ? Wih : (g == 2) ? Wgh : Woh;
    int k0 = blockIdx.x * 32, j0 = blockIdx.y * 32;
    int tx = threadIdx.x, ty = threadIdx.y;
#pragma unroll
    for (int i = 0; i < 32; i += 8)
        tile[ty + i][tx] = W[(size_t)(k0 + ty + i) * 1024 + j0 + tx];
    __syncthreads();
#pragma unroll
    for (int i = 0; i < 32; i += 8)
        g_Wt[((size_t)g * 1024 + (j0 + ty + i)) * 1024 + (k0 + tx)] =
            __float2bfloat16(tile[tx][ty + i]);
}

// ---------------- prep 3: gate-input table G[c][j][g] ----------------
__global__ void compute_G(const float* __restrict__ emb,
                          const float* __restrict__ Wfx, const float* __restrict__ Wix,
                          const float* __restrict__ Wgx, const float* __restrict__ Wox,
                          const float* __restrict__ bfp, const float* __restrict__ bip,
                          const float* __restrict__ bgp, const float* __restrict__ bop) {
    int g = blockIdx.z;
    const float* Wx   = (g == 0) ? Wfx : (g == 1) ? Wix : (g == 2) ? Wgx : Wox;
    const float* bias = (g == 0) ? bfp : (g == 1) ? bip : (g == 2) ? bgp : bop;
    int j0 = blockIdx.x * 128, c0 = blockIdx.y * 16;
    __shared__ float es[16][512];
    int tid = threadIdx.x;
    for (int idx = tid; idx < 16 * 512; idx += 256) {
        int cc = idx >> 9, d = idx & 511;
        int c = c0 + cc;
        es[cc][d] = (c <= NC_) ? emb[c * 512 + d] : 0.f;
    }
    __syncthreads();
    int tc = tid >> 4, tj = tid & 15;
    float acc[8];
#pragma unroll
    for (int m = 0; m < 8; m++) acc[m] = 0.f;
    for (int d = 0; d < 512; d++) {
        float e = es[tc][d];
        const float* wr = Wx + (size_t)d * 1024 + j0 + tj;
#pragma unroll
        for (int m = 0; m < 8; m++) acc[m] = fmaf(e, wr[m * 16], acc[m]);
    }
    int c = c0 + tc;
    if (c <= NC_) {
#pragma unroll
        for (int m = 0; m < 8; m++) {
            int j = j0 + tj + m * 16;
            g_G[((size_t)c * 1024 + j) * 4 + g] = acc[m] + bias[j];
        }
    }
}

// ---------------- persistent recurrence ----------------
// 128 CTAs x 320 threads. Warps 0-3 & 4-7: K-split consumers (warp w and w+4 own
// b-rows 32(w&3)..+31; w handles K-chunks 0-7, w+4 chunks 8-15). Warps 8,9: bulk
// producers (stream A: chunks 0-7 -> bufs 0-3; stream B: chunks 8-15 -> bufs 4-7).
// Cross-CTA sync: per-group flags g_prod[16] (chunk kc written by CTAs 8kc..8kc+7).
__global__ void __launch_bounds__(NTHR, 1) lstm_persistent(const int* __restrict__ x) {
    extern __shared__ char smem[];
    uint32_t sbase = (uint32_t)__cvta_generic_to_shared(smem);
    const uint32_t mb_full = sbase;          // 8 x 8 B
    const uint32_t mb_cons = sbase + 64;     // 8 x 8 B
    __nv_bfloat16* ws = (__nv_bfloat16*)(smem + 128);
    char*          hring = smem + RING_OFF;
    const uint32_t hring_s = sbase + RING_OFF;
    float*         reds = (float*)(smem + REDS_OFF);

    const int tid = threadIdx.x, warp = tid >> 5, lane = tid & 31;
    const int wg = warp & 3;
    const int r = lane >> 2, q = lane & 3;
    const int cta = blockIdx.x;

    if (tid == 0) {
#pragma unroll
        for (int i = 0; i < 8; i++) { MBAR_INIT(mb_full + 8 * i, 1); MBAR_INIT(mb_cons + 8 * i, 128); }
    }
    // one-time W fill: ws[n][p] = Wt[gate][cta*8+jl][perm^-1(p)], n = gate*8+jl
    for (int t = tid; t < 32 * 1024; t += NTHR) {
        int n = t >> 10, p = t & 1023;
        int gate = n >> 3, jl = n & 7;
        int korig = (p & ~15) + c_kmap[p & 15];
        ws[n * WK + p] = g_Wt[((size_t)(gate << 10) + cta * NJ + jl) * 1024 + korig];
    }
    __syncthreads();

    float C[2][2][2];
#pragma unroll
    for (int a = 0; a < 2; a++)
#pragma unroll
        for (int b = 0; b < 2; b++) { C[a][b][0] = 0.f; C[a][b][1] = 0.f; }

    const float4* G4 = (const float4*)g_G;

    if (warp >= 8) {                          // ================ producers ================
        if (lane == 0) {
            const int kcBase = (warp - 8) * 8, bufBase = (warp - 8) * 4;
#pragma unroll 1
            for (int s = 0; s < S_; s++) {
                const char* hg = (const char*)g_h[s & 1];
#pragma unroll 1
                for (int i = 0; i < 8; i++) {
                    int kc = kcBase + i, buf = bufBase + (i & 3), g = (i >> 2) & 1;
                    if (s > 0) {              // wait for writers of this chunk (step s-1 epilogues)
                        unsigned target = 8u * (unsigned)s, v;
                        do {
                            asm volatile("ld.acquire.gpu.u32 %0, [%1];"
                                         : "=r"(v) : "l"(&g_prod[kc]) : "memory");
                        } while (v < target);
                    }
                    if (!(s == 0 && i < 4))   // ring WAR: previous use consumed
                        MBAR_WAIT(mb_cons + 8 * buf, g ^ 1);
                    MBAR_EXPECT_TX(mb_full + 8 * buf, (uint32_t)CHUNK_B);
                    bulk_cp(hring_s + (uint32_t)buf * CHUNK_B, hg + (size_t)kc * CHUNK_B,
                            CHUNK_B, mb_full + 8 * buf);
                }
            }
        }
        return;
    }

    // ================ consumers ================
    const int kcBase = (warp >> 2) * 8, bufBase = (warp >> 2) * 4;
    const bool epi = (warp < 4);

#pragma unroll 1
    for (int s = 0; s < S_; s++) {
        char* hw = (char*)g_h[(s & 1) ^ 1];

        int cid[4];
        if (epi) {
#pragma unroll
            for (int mt = 0; mt < 2; mt++)
#pragma unroll
                for (int hh = 0; hh < 2; hh++)
                    cid[mt * 2 + hh] = __ldg(&x[(32 * wg + 16 * mt + 8 * hh + r) * S_ + s]);
        }

        float acc[2][4][4];
#pragma unroll
        for (int mt = 0; mt < 2; mt++)
#pragma unroll
            for (int t = 0; t < 4; t++)
#pragma unroll
                for (int i = 0; i < 4; i++) acc[mt][t][i] = 0.f;

#pragma unroll 1
        for (int i = 0; i < 8; i++) {
            int buf = bufBase + (i & 3), par = (i >> 2) & 1;
            int kc = kcBase + i;
            MBAR_WAIT(mb_full + 8 * buf, par);
            const char* hb = hring + (size_t)buf * CHUNK_B;
#pragma unroll
            for (int ks = 0; ks < 4; ks++) {
                const char* ab = hb + ks * 4096 + q * 8;
                uint2 A00 = *(const uint2*)(ab + (32 * wg + r) * 32);
                uint2 A01 = *(const uint2*)(ab + (32 * wg + r + 8) * 32);
                uint2 A10 = *(const uint2*)(ab + (32 * wg + 16 + r) * 32);
                uint2 A11 = *(const uint2*)(ab + (32 * wg + 24 + r) * 32);
                const __nv_bfloat16* wb = ws + (size_t)r * WK + kc * 64 + ks * 16 + q * 4;
#pragma unroll
                for (int t = 0; t < 4; t++) {
                    uint2 Bv = *(const uint2*)(wb + (size_t)t * 8 * WK);
                    mma16816(acc[0][t], A00.x, A01.x, A00.y, A01.y, Bv.x, Bv.y);
                    mma16816(acc[1][t], A10.x, A11.x, A10.y, A11.y, Bv.x, Bv.y);
                }
            }
            MBAR_ARRIVE(mb_cons + 8 * buf);
        }

        if (!epi) {
            // warps 4-7: publish partial sums, then hand off
            int slot = tid - 128;
#pragma unroll
            for (int f = 0; f < 32; f++) reds[f * 128 + slot] = ((float*)acc)[f];
            BARX(1, 256);                     // partials visible to warps 0-3
            BARX(2, 256);                     // warps 0-3 done reading -> safe to loop
        } else {
            BARX(1, 256);
#pragma unroll
            for (int f = 0; f < 32; f++) ((float*)acc)[f] += reds[f * 128 + tid];
            BARX(2, 256);

            // ---- epilogue: gates, C, h ----
            const int bk = cta >> 1;
            const int poff = 8 * q + 4 * (cta & 1);
#pragma unroll
            for (int mt = 0; mt < 2; mt++) {
#pragma unroll
                for (int hh = 0; hh < 2; hh++) {
                    int b = 32 * wg + 16 * mt + 8 * hh + r;
                    int id = cid[mt * 2 + hh];
                    float4 Ga = __ldg(&G4[(size_t)id * 1024 + cta * NJ + 2 * q]);
                    float4 Gb = __ldg(&G4[(size_t)id * 1024 + cta * NJ + 2 * q + 1]);
                    int c0 = hh * 2;
                    float f0 = sigm(acc[mt][0][c0] + Ga.x);
                    float i0 = sigm(acc[mt][1][c0] + Ga.y);
                    float g0 = sigm(acc[mt][2][c0] + Ga.z);
                    float o0 = sigm(acc[mt][3][c0] + Ga.w);
                    float f1 = sigm(acc[mt][0][c0 + 1] + Gb.x);
                    float i1 = sigm(acc[mt][1][c0 + 1] + Gb.y);
                    float g1 = sigm(acc[mt][2][c0 + 1] + Gb.z);
                    float o1 = sigm(acc[mt][3][c0 + 1] + Gb.w);
                    float Cn0 = (id > 0) ? fmaf(C[mt][hh][0], f0, g0 * i0) : 0.f;
                    float Cn1 = (id > 0) ? fmaf(C[mt][hh][1], f1, g1 * i1) : 0.f;
                    C[mt][hh][0] = Cn0;
                    C[mt][hh][1] = Cn1;
                    float h0 = o0 * tanha(Cn0);
                    float h1 = o1 * tanha(Cn1);
                    __nv_bfloat162 hp = __floats2bfloat162_rn(h0, h1);
                    *(uint32_t*)(hw + (size_t)bk * 4096 + b * 32 + poff) = *(uint32_t*)&hp;
                    if (s == S_ - 1) {
                        g_hfin[(size_t)b * 1024 + cta * NJ + 2 * q]     = h0;
                        g_hfin[(size_t)b * 1024 + cta * NJ + 2 * q + 1] = h1;
                    }
                }
            }
            asm volatile("fence.proxy.async;" ::: "memory");
            __threadfence();                  // release h stores to GPU scope
            BARX(3, 128);                     // all 4 epilogue warps done
            if (tid == 0) atomicAdd(&g_prod[cta >> 3], 1u);
        }
    }
}

// ---------------- final projection + log_softmax ----------------
__global__ void proj_kernel(const float* __restrict__ Wph, const float* __restrict__ bp,
                            float* __restrict__ out) {
    __shared__ float hrow[1024];
    __shared__ float redmax[4], redsum[4];
    int b = blockIdx.x, tid = threadIdx.x;
    for (int i = tid; i < 1024; i += 128) hrow[i] = g_hfin[b * 1024 + i];
    __syncthreads();
    float acc = bp[tid];
#pragma unroll 8
    for (int j = 0; j < 1024; j++) acc = fmaf(hrow[j], Wph[j * 128 + tid], acc);
    float m = acc;
#pragma unroll
    for (int o = 16; o; o >>= 1) m = fmaxf(m, __shfl_xor_sync(0xffffffffu, m, o));
    if ((tid & 31) == 0) redmax[tid >> 5] = m;
    __syncthreads();
    m = fmaxf(fmaxf(redmax[0], redmax[1]), fmaxf(redmax[2], redmax[3]));
    float e = expf(acc - m);
    float ss = e;
#pragma unroll
    for (int o = 16; o; o >>= 1) ss += __shfl_xor_sync(0xffffffffu, ss, o);
    if ((tid & 31) == 0) redsum[tid >> 5] = ss;
    __syncthreads();
    float tot = redsum[0] + redsum[1] + redsum[2] + redsum[3];
    out[b * 128 + tid] = acc - m - logf(tot);
}

// ---------------- launch ----------------
extern "C" void kernel_launch(void* const* d_in, const int* in_sizes, int n_in,
                              void* d_out, int out_size) {
    const int*   x   = (const int*)d_in[0];
    const float* emb = (const float*)d_in[1];
    const float* Wfx = (const float*)d_in[2];
    const float* Wfh = (const float*)d_in[3];
    const float* bfp = (const float*)d_in[4];
    const float* Wix = (const float*)d_in[5];
    const float* Wih = (const float*)d_in[6];
    const float* bip = (const float*)d_in[7];
    const float* Wgx = (const float*)d_in[8];
    const float* Wgh = (const float*)d_in[9];
    const float* bgp = (const float*)d_in[10];
    const float* Wox = (const float*)d_in[11];
    const float* Woh = (const float*)d_in[12];
    const float* bop = (const float*)d_in[13];
    const float* Wph = (const float*)d_in[14];
    const float* bpp = (const float*)d_in[15];
    float* out = (float*)d_out;

    cudaFuncSetAttribute(lstm_persistent, cudaFuncAttributeMaxDynamicSharedMemorySize, SMEM_TOTAL);

    init_state<<<512, 256>>>();
    transpose_W<<<dim3(32, 32, 4), dim3(32, 8)>>>(Wfh, Wih, Wgh, Woh);
    compute_G<<<dim3(8, 9, 4), 256>>>(emb, Wfx, Wix, Wgx, Wox, bfp, bip, bgp, bop);
    lstm_persistent<<<NCTA, NTHR, SMEM_TOTAL>>>(x);
    proj_kernel<<<128, 128>>>(Wph, bpp, out);
}